// round 7
// baseline (speedup 1.0000x reference)
#include <cuda_runtime.h>

#define N_ROWS 8192
#define D_DIM  1024
#define THREADS 256
#define NBLOCKS 1024
#define WARPS_PER_BLOCK (THREADS / 32)                   // 8
#define F4_PER_LANE (D_DIM / 4 / 32)                     // 8

__device__ float        g_partial[NBLOCKS];
__device__ unsigned int g_count = 0;

__global__ __launch_bounds__(THREADS, 7)   // R4-best: 7 CTAs/SM, single wave, regs<=36
void fused_cosine_mse_kernel(const float* __restrict__ A,
                             const float* __restrict__ B,
                             const float* __restrict__ labels,
                             float* __restrict__ out) {
    const int t   = threadIdx.x;
    const int wid = t >> 5;
    const int lid = t & 31;
    const int row = blockIdx.x * WARPS_PER_BLOCK + wid;   // one row per warp

    const float4* a4 = reinterpret_cast<const float4*>(A + (size_t)row * D_DIM) + lid;
    const float4* b4 = reinterpret_cast<const float4*>(B + (size_t)row * D_DIM) + lid;

    const float label = labels[row];   // overlaps with the streaming loads

    // Front-batch all 16 loads (streaming: no reuse, evict-first)
    float4 av[F4_PER_LANE], bv[F4_PER_LANE];
    #pragma unroll
    for (int k = 0; k < F4_PER_LANE; k++) {
        av[k] = __ldcs(a4 + k * 32);
        bv[k] = __ldcs(b4 + k * 32);
    }
    // Scheduling fence: keep compute from being hoisted between the loads
    asm volatile("" ::: "memory");

    float dot = 0.0f, na = 0.0f, nb = 0.0f;
    #pragma unroll
    for (int k = 0; k < F4_PER_LANE; k++) {
        dot += av[k].x * bv[k].x + av[k].y * bv[k].y + av[k].z * bv[k].z + av[k].w * bv[k].w;
        na  += av[k].x * av[k].x + av[k].y * av[k].y + av[k].z * av[k].z + av[k].w * av[k].w;
        nb  += bv[k].x * bv[k].x + bv[k].y * bv[k].y + bv[k].z * bv[k].z + bv[k].w * bv[k].w;
    }

    // Butterfly reduce: every lane ends with full-row sums
    #pragma unroll
    for (int off = 16; off > 0; off >>= 1) {
        dot += __shfl_xor_sync(0xFFFFFFFFu, dot, off);
        na  += __shfl_xor_sync(0xFFFFFFFFu, na,  off);
        nb  += __shfl_xor_sync(0xFFFFFFFFu, nb,  off);
    }

    const float score = dot * rsqrtf(na * nb);
    const float diff  = score - label;
    const float acc   = diff * diff;

    // Block reduction of 8 warp values
    __shared__ float s_warp[WARPS_PER_BLOCK];
    __shared__ bool  s_is_last;
    if (lid == 0) s_warp[wid] = acc;
    __syncthreads();

    if (t == 0) {
        float bsum = 0.0f;
        #pragma unroll
        for (int w = 0; w < WARPS_PER_BLOCK; w++) bsum += s_warp[w];
        g_partial[blockIdx.x] = bsum;
        __threadfence();
        const unsigned int prev = atomicAdd(&g_count, 1u);
        s_is_last = (prev == NBLOCKS - 1);
    }
    __syncthreads();

    if (s_is_last) {
        __threadfence();   // acquire: all g_partial writes visible
        // One coalesced float4 burst: 256 threads x 4 partials each (fixed slots -> deterministic)
        const float4 p = reinterpret_cast<const float4*>(g_partial)[t];
        float v = (p.x + p.y) + (p.z + p.w);

        #pragma unroll
        for (int off = 16; off > 0; off >>= 1)
            v += __shfl_xor_sync(0xFFFFFFFFu, v, off);

        __shared__ float s_final[WARPS_PER_BLOCK];
        if (lid == 0) s_final[wid] = v;
        __syncthreads();

        if (t == 0) {
            float total = 0.0f;
            #pragma unroll
            for (int w = 0; w < WARPS_PER_BLOCK; w++) total += s_final[w];
            out[0] = total * (1.0f / (float)N_ROWS);
            g_count = 0;   // reset for next graph replay
        }
    }
}

extern "C" void kernel_launch(void* const* d_in, const int* in_sizes, int n_in,
                              void* d_out, int out_size) {
    const float* A      = (const float*)d_in[0];  // issues_1_geb [8192,1024]
    const float* B      = (const float*)d_in[1];  // issues_2_geb [8192,1024]
    const float* labels = (const float*)d_in[2];  // labels [8192]
    float* out = (float*)d_out;

    fused_cosine_mse_kernel<<<NBLOCKS, THREADS>>>(A, B, labels, out);
}

// round 8
// speedup vs baseline: 1.2179x; 1.2179x over previous
#include <cuda_runtime.h>

#define N_ROWS 8192
#define D_DIM  1024
#define THREADS 256
#define NBLOCKS 1024
#define WARPS_PER_BLOCK (THREADS / 32)                   // 8
#define F4_PER_LANE (D_DIM / 4 / 32)                     // 8
#define PARTIALS_PER_THREAD (NBLOCKS / THREADS)          // 4

__device__ float        g_partial[NBLOCKS];
__device__ unsigned int g_count = 0;

__global__ __launch_bounds__(THREADS, 7)   // R4-best: regs<=36 -> 7 CTAs/SM, single wave
void fused_cosine_mse_kernel(const float* __restrict__ A,
                             const float* __restrict__ B,
                             const float* __restrict__ labels,
                             float* __restrict__ out) {
    const int t   = threadIdx.x;
    const int wid = t >> 5;
    const int lid = t & 31;
    const int row = blockIdx.x * WARPS_PER_BLOCK + wid;   // one row per warp

    const float4* a4 = reinterpret_cast<const float4*>(A + (size_t)row * D_DIM) + lid;
    const float4* b4 = reinterpret_cast<const float4*>(B + (size_t)row * D_DIM) + lid;

    // Front-batch all 16 loads (streaming: no reuse, evict-first)
    float4 av[F4_PER_LANE], bv[F4_PER_LANE];
    #pragma unroll
    for (int k = 0; k < F4_PER_LANE; k++) {
        av[k] = __ldcs(a4 + k * 32);
        bv[k] = __ldcs(b4 + k * 32);
    }
    // Scheduling fence: keep compute from being hoisted between the loads
    asm volatile("" ::: "memory");

    float dot = 0.0f, na = 0.0f, nb = 0.0f;
    #pragma unroll
    for (int k = 0; k < F4_PER_LANE; k++) {
        dot += av[k].x * bv[k].x + av[k].y * bv[k].y + av[k].z * bv[k].z + av[k].w * bv[k].w;
        na  += av[k].x * av[k].x + av[k].y * av[k].y + av[k].z * av[k].z + av[k].w * av[k].w;
        nb  += bv[k].x * bv[k].x + bv[k].y * bv[k].y + bv[k].z * bv[k].z + bv[k].w * bv[k].w;
    }

    // Butterfly reduce: every lane ends with full-row sums
    #pragma unroll
    for (int off = 16; off > 0; off >>= 1) {
        dot += __shfl_xor_sync(0xFFFFFFFFu, dot, off);
        na  += __shfl_xor_sync(0xFFFFFFFFu, na,  off);
        nb  += __shfl_xor_sync(0xFFFFFFFFu, nb,  off);
    }

    const float score = dot * rsqrtf(na * nb);
    const float diff  = score - labels[row];   // broadcast read per warp
    const float acc   = diff * diff;

    // Block reduction of 8 warp values
    __shared__ float s_warp[WARPS_PER_BLOCK];
    __shared__ bool  s_is_last;
    if (lid == 0) s_warp[wid] = acc;
    __syncthreads();

    if (t == 0) {
        float bsum = 0.0f;
        #pragma unroll
        for (int w = 0; w < WARPS_PER_BLOCK; w++) bsum += s_warp[w];
        g_partial[blockIdx.x] = bsum;
        __threadfence();
        const unsigned int prev = atomicAdd(&g_count, 1u);
        s_is_last = (prev == NBLOCKS - 1);
    }
    __syncthreads();

    if (s_is_last) {
        __threadfence();   // acquire: all g_partial writes visible
        // Deterministic fixed-slot folding: thread t sums partials t, t+256, ...
        float v = 0.0f;
        #pragma unroll
        for (int i = 0; i < PARTIALS_PER_THREAD; i++)
            v += g_partial[t + i * THREADS];

        #pragma unroll
        for (int off = 16; off > 0; off >>= 1)
            v += __shfl_xor_sync(0xFFFFFFFFu, v, off);

        __shared__ float s_final[WARPS_PER_BLOCK];
        if (lid == 0) s_final[wid] = v;
        __syncthreads();

        if (t == 0) {
            float total = 0.0f;
            #pragma unroll
            for (int w = 0; w < WARPS_PER_BLOCK; w++) total += s_final[w];
            out[0] = total * (1.0f / (float)N_ROWS);
            g_count = 0;   // reset for next graph replay
        }
    }
}

extern "C" void kernel_launch(void* const* d_in, const int* in_sizes, int n_in,
                              void* d_out, int out_size) {
    const float* A      = (const float*)d_in[0];  // issues_1_geb [8192,1024]
    const float* B      = (const float*)d_in[1];  // issues_2_geb [8192,1024]
    const float* labels = (const float*)d_in[2];  // labels [8192]
    float* out = (float*)d_out;

    fused_cosine_mse_kernel<<<NBLOCKS, THREADS>>>(A, B, labels, out);
}